// round 9
// baseline (speedup 1.0000x reference)
#include <cuda_runtime.h>
#include <cuda_fp16.h>
#include <math.h>

#define TOT     128000
#define HDIM    64
#define NHEADS  4
#define DHEAD   16
#define FIN     32
#define NEDGE   512000
#define NB      128
#define OBSD    1500
#define HSD     512
#define NOUTD   15
#define VHD     128
#define NA      15
#define NLAYER  4

// ---------------- scratch (device globals; no allocation allowed) ----------------
__device__ __align__(16) __half g_x16[TOT * HDIM];
__device__ __align__(16) __half g_q16[TOT * HDIM];
__device__ __align__(16) __half g_kv16[TOT * 128];     // packed k|v per node
__device__ __align__(16) __half g_buf16[TOT * HDIM];   // attention aggregate
__device__ __align__(16) __half g_hid16[TOT * 2 * HDIM];
__device__ __align__(16) __half g_nf16[TOT * FIN];
// fp16 weights
__device__ __align__(16) __half g_w_in16[FIN * HDIM];
__device__ __align__(16) __half g_wqkv16[NLAYER * HDIM * 192];
__device__ __align__(16) __half g_wo16[NLAYER * HDIM * HDIM];
__device__ __align__(16) __half g_w1_16[NLAYER * HDIM * 2 * HDIM];
__device__ __align__(16) __half g_w2_16[NLAYER * 2 * HDIM * HDIM];
// CSR
__device__ int g_counts[TOT];
__device__ int g_fill[TOT];
__device__ int g_rowptr[TOT + 1];
__device__ int g_csrc[NEDGE];
// heads (fp32)
__device__ __align__(16) float g_gat[NB * NA];
__device__ __align__(16) float g_feat[NB * HSD];
__device__ __align__(16) float g_feat2[NB * HSD];
__device__ __align__(16) float g_vh[NB * VHD];
__device__ __align__(16) float g_vh2[NB * VHD];

// ---------------- CSR build ----------------
__global__ void zero_counts_kernel() {
    int i = blockIdx.x * blockDim.x + threadIdx.x;
    if (i < TOT) { g_counts[i] = 0; g_fill[i] = 0; }
}

__global__ void count_edges_kernel(const int* __restrict__ edge_dst) {
    int e = blockIdx.x * blockDim.x + threadIdx.x;
    if (e < NEDGE) atomicAdd(&g_counts[edge_dst[e]], 1);
}

__global__ void scan_kernel() {
    __shared__ int wsum[32];
    __shared__ int carry;
    int tid = threadIdx.x;
    int lane = tid & 31, wid = tid >> 5;
    if (tid == 0) carry = 0;
    __syncthreads();
    for (int base = 0; base < TOT; base += 1024) {
        int i = base + tid;
        int val = (i < TOT) ? g_counts[i] : 0;
        int s = val;
        #pragma unroll
        for (int off = 1; off < 32; off <<= 1) {
            int t = __shfl_up_sync(0xffffffffu, s, off);
            if (lane >= off) s += t;
        }
        if (lane == 31) wsum[wid] = s;
        __syncthreads();
        if (wid == 0) {
            int ws = wsum[lane];
            #pragma unroll
            for (int off = 1; off < 32; off <<= 1) {
                int t = __shfl_up_sync(0xffffffffu, ws, off);
                if (lane >= off) ws += t;
            }
            wsum[lane] = ws;
        }
        __syncthreads();
        int pre = (wid > 0) ? wsum[wid - 1] : 0;
        int incl = pre + s;
        if (i < TOT) g_rowptr[i] = carry + incl - val;
        __syncthreads();
        if (tid == 0) carry += wsum[31];
        __syncthreads();
    }
    if (tid == 0) g_rowptr[TOT] = carry;
}

__global__ void scatter_edges_kernel(const int* __restrict__ edge_src,
                                     const int* __restrict__ edge_dst) {
    int e = blockIdx.x * blockDim.x + threadIdx.x;
    if (e < NEDGE) {
        int d = edge_dst[e];
        int pos = atomicAdd(&g_fill[d], 1);
        g_csrc[g_rowptr[d] + pos] = edge_src[e];
    }
}

// ---------------- fp32 -> fp16 conversion / weight packing ----------------
__global__ void convert_f16_kernel(const float* __restrict__ src, __half* __restrict__ dst, int n) {
    int i = blockIdx.x * blockDim.x + threadIdx.x;
    if (i < n) dst[i] = __float2half(src[i]);
}

__global__ void pack_qkv_f16_kernel(const float* __restrict__ Wq,
                                    const float* __restrict__ Wk,
                                    const float* __restrict__ Wv) {
    int idx = blockIdx.x * blockDim.x + threadIdx.x;
    if (idx >= NLAYER * HDIM * HDIM) return;
    int l = idx >> 12;
    int rem = idx & 4095;
    int k = rem >> 6, c = rem & 63;
    __half* dst = &g_wqkv16[(l * HDIM + k) * 192];
    dst[c]       = __float2half(Wq[idx]);
    dst[64 + c]  = __float2half(Wk[idx]);
    dst[128 + c] = __float2half(Wv[idx]);
}

// ---------------- fp16 tensor-core GEMM (m16n8k16, fp32 accum) ----------------
// A fp16 [M][K], B fp16 [K][N] row-major, BM=128, BN=64, BK=32, 256 threads.
// Warp w owns rows [16w,16w+16), 8 n-tiles. Fragments:
//  a0={A[g][2t],A[g][2t+1]}, a1=rows+8, a2=cols+8, a3=both.
//  b0={B[2t][n],B[2t+1][n]}, b1=k+8 rows  -> stored pair-packed in Bs_pack[k2][n].

struct GemmSmem {
    __half As[128][40];            // stride 40 halfs: frag banks (20g+t) all distinct
    __half2 Bs[16][72];            // stride 72: banks (8t+g) distinct
};

#define GEMM_STAGE(Aptr, Bptr, Kdim, Ndim, bnoff)                                   \
    {                                                                               \
        /* A chunk: 128 rows x 32 halfs */                                          \
        _Pragma("unroll")                                                           \
        for (int i = 0; i < 2; i++) {                                               \
            int idx = i * 256 + tid;          /* 0..511 uint4 units */              \
            int r = idx >> 2;                                                       \
            int cu = (idx & 3) * 8;                                                 \
            uint4 v = *(const uint4*)&Aptr[(size_t)(bm + r) * Kdim + k0 + cu];      \
            *(uint4*)&sm->As[r][cu] = v;                                            \
        }                                                                           \
        /* B chunk: 32 rows x 64 cols, pair-packed */                               \
        {                                                                           \
            int k2 = tid >> 4;                 /* 0..15 */                          \
            int n0 = (tid & 15) * 4;                                                \
            const __half* b0p = &Bptr[(size_t)(k0 + 2 * k2) * Ndim + bnoff + n0];   \
            const __half* b1p = b0p + Ndim;                                         \
            _Pragma("unroll")                                                       \
            for (int u = 0; u < 4; u++)                                             \
                sm->Bs[k2][n0 + u] = __halves2half2(b0p[u], b1p[u]);                \
        }                                                                           \
    }

#define GEMM_MAINLOOP()                                                             \
    _Pragma("unroll")                                                               \
    for (int s = 0; s < 2; s++) {                                                   \
        unsigned a0 = *(const unsigned*)&sm->As[warp * 16 + g][16 * s + 2 * t];     \
        unsigned a1 = *(const unsigned*)&sm->As[warp * 16 + g + 8][16 * s + 2 * t]; \
        unsigned a2 = *(const unsigned*)&sm->As[warp * 16 + g][16 * s + 2 * t + 8]; \
        unsigned a3 = *(const unsigned*)&sm->As[warp * 16 + g + 8][16 * s + 2 * t + 8];\
        _Pragma("unroll")                                                           \
        for (int j = 0; j < 8; j++) {                                               \
            unsigned b0 = *(const unsigned*)&sm->Bs[8 * s + t][8 * j + g];          \
            unsigned b1 = *(const unsigned*)&sm->Bs[8 * s + t + 4][8 * j + g];      \
            asm volatile(                                                           \
                "mma.sync.aligned.m16n8k16.row.col.f32.f16.f16.f32 "                \
                "{%0,%1,%2,%3}, {%4,%5,%6,%7}, {%8,%9}, {%0,%1,%2,%3};"             \
                : "+f"(acc[j][0]), "+f"(acc[j][1]), "+f"(acc[j][2]), "+f"(acc[j][3])\
                : "r"(a0), "r"(a1), "r"(a2), "r"(a3), "r"(b0), "r"(b1));            \
        }                                                                           \
    }

// plain GEMM: C fp16 [M][N] (+bias fp32)(+relu)
__global__ __launch_bounds__(256) void gemm_f16_kernel(
    const __half* __restrict__ A, const __half* __restrict__ B,
    const float* __restrict__ bias, __half* __restrict__ C,
    int N, int K, int act)
{
    __shared__ GemmSmem smem;
    GemmSmem* sm = &smem;
    int bm = blockIdx.y * 128, bn = blockIdx.x * 64;
    int tid = threadIdx.x;
    int warp = tid >> 5, lane = tid & 31;
    int g = lane >> 2, t = lane & 3;

    float acc[8][4];
    #pragma unroll
    for (int j = 0; j < 8; j++)
        #pragma unroll
        for (int i = 0; i < 4; i++) acc[j][i] = 0.0f;

    for (int k0 = 0; k0 < K; k0 += 32) {
        GEMM_STAGE(A, B, K, N, bn)
        __syncthreads();
        GEMM_MAINLOOP()
        __syncthreads();
    }
    int row0 = bm + warp * 16 + g;
    #pragma unroll
    for (int j = 0; j < 8; j++) {
        int col = bn + j * 8 + 2 * t;
        float v0 = acc[j][0], v1 = acc[j][1], v2 = acc[j][2], v3 = acc[j][3];
        if (bias) {
            float bb0 = bias[col], bb1 = bias[col + 1];
            v0 += bb0; v1 += bb1; v2 += bb0; v3 += bb1;
        }
        if (act) {
            v0 = fmaxf(v0, 0.0f); v1 = fmaxf(v1, 0.0f);
            v2 = fmaxf(v2, 0.0f); v3 = fmaxf(v3, 0.0f);
        }
        *(__half2*)&C[(size_t)row0 * N + col] = __float22half2_rn(make_float2(v0, v1));
        *(__half2*)&C[(size_t)(row0 + 8) * N + col] = __float22half2_rn(make_float2(v2, v3));
    }
}

// fused QKV: A[M,64] @ Wqkv[64,192]; bn 0 -> q (ld 64), bn 1,2 -> kv (ld 128)
__global__ __launch_bounds__(256) void gemm_f16_qkv_kernel(
    const __half* __restrict__ A, const __half* __restrict__ B,
    __half* __restrict__ Cq, __half* __restrict__ Ckv)
{
    const int N = 192, K = 64;
    __shared__ GemmSmem smem;
    GemmSmem* sm = &smem;
    int bm = blockIdx.y * 128, bn = blockIdx.x * 64;
    int tid = threadIdx.x;
    int warp = tid >> 5, lane = tid & 31;
    int g = lane >> 2, t = lane & 3;

    float acc[8][4];
    #pragma unroll
    for (int j = 0; j < 8; j++)
        #pragma unroll
        for (int i = 0; i < 4; i++) acc[j][i] = 0.0f;

    for (int k0 = 0; k0 < K; k0 += 32) {
        GEMM_STAGE(A, B, K, N, bn)
        __syncthreads();
        GEMM_MAINLOOP()
        __syncthreads();
    }
    __half* Cout;
    int ldc, coff;
    if (blockIdx.x == 0) { Cout = Cq; ldc = 64; coff = 0; }
    else { Cout = Ckv; ldc = 128; coff = (blockIdx.x - 1) * 64; }
    int row0 = bm + warp * 16 + g;
    #pragma unroll
    for (int j = 0; j < 8; j++) {
        int col = coff + j * 8 + 2 * t;
        *(__half2*)&Cout[(size_t)row0 * ldc + col] =
            __float22half2_rn(make_float2(acc[j][0], acc[j][1]));
        *(__half2*)&Cout[(size_t)(row0 + 8) * ldc + col] =
            __float22half2_rn(make_float2(acc[j][2], acc[j][3]));
    }
}

// GEMM (N=64) + bias + residual + LayerNorm epilogue, X fp16 in-place.
__global__ __launch_bounds__(256) void gemm_f16_ln_kernel(
    const __half* __restrict__ A, const __half* __restrict__ B,
    const float* __restrict__ bias, __half* __restrict__ X,
    const float* __restrict__ gamma, const float* __restrict__ beta,
    int K)
{
    const int N = 64;
    __shared__ GemmSmem smem;
    GemmSmem* sm = &smem;
    int bm = blockIdx.y * 128;
    const int bn = 0;
    int tid = threadIdx.x;
    int warp = tid >> 5, lane = tid & 31;
    int g = lane >> 2, t = lane & 3;

    float acc[8][4];
    #pragma unroll
    for (int j = 0; j < 8; j++)
        #pragma unroll
        for (int i = 0; i < 4; i++) acc[j][i] = 0.0f;

    for (int k0 = 0; k0 < K; k0 += 32) {
        GEMM_STAGE(A, B, K, N, bn)
        __syncthreads();
        GEMM_MAINLOOP()
        __syncthreads();
    }

    int row0 = bm + warp * 16 + g;
    int row1 = row0 + 8;
    float sum0 = 0.0f, sum1 = 0.0f;
    #pragma unroll
    for (int j = 0; j < 8; j++) {
        int col = j * 8 + 2 * t;
        float bb0 = 0.0f, bb1 = 0.0f;
        if (bias) { bb0 = bias[col]; bb1 = bias[col + 1]; }
        float2 r0 = __half22float2(*(const __half2*)&X[(size_t)row0 * N + col]);
        float2 r1 = __half22float2(*(const __half2*)&X[(size_t)row1 * N + col]);
        acc[j][0] += bb0 + r0.x; acc[j][1] += bb1 + r0.y;
        acc[j][2] += bb0 + r1.x; acc[j][3] += bb1 + r1.y;
        sum0 += acc[j][0] + acc[j][1];
        sum1 += acc[j][2] + acc[j][3];
    }
    sum0 += __shfl_xor_sync(0xffffffffu, sum0, 1);
    sum0 += __shfl_xor_sync(0xffffffffu, sum0, 2);
    sum1 += __shfl_xor_sync(0xffffffffu, sum1, 1);
    sum1 += __shfl_xor_sync(0xffffffffu, sum1, 2);
    float m0 = sum0 * (1.0f / 64.0f);
    float m1 = sum1 * (1.0f / 64.0f);
    float var0 = 0.0f, var1 = 0.0f;
    #pragma unroll
    for (int j = 0; j < 8; j++) {
        float d0 = acc[j][0] - m0, d1 = acc[j][1] - m0;
        float d2 = acc[j][2] - m1, d3 = acc[j][3] - m1;
        var0 += d0 * d0 + d1 * d1;
        var1 += d2 * d2 + d3 * d3;
    }
    var0 += __shfl_xor_sync(0xffffffffu, var0, 1);
    var0 += __shfl_xor_sync(0xffffffffu, var0, 2);
    var1 += __shfl_xor_sync(0xffffffffu, var1, 1);
    var1 += __shfl_xor_sync(0xffffffffu, var1, 2);
    float rs0 = rsqrtf(var0 * (1.0f / 64.0f) + 1e-5f);
    float rs1 = rsqrtf(var1 * (1.0f / 64.0f) + 1e-5f);
    #pragma unroll
    for (int j = 0; j < 8; j++) {
        int col = j * 8 + 2 * t;
        float gg0 = gamma[col], gg1 = gamma[col + 1];
        float bb0 = beta[col], bb1 = beta[col + 1];
        float w0 = (acc[j][0] - m0) * rs0 * gg0 + bb0;
        float w1 = (acc[j][1] - m0) * rs0 * gg1 + bb1;
        float w2 = (acc[j][2] - m1) * rs1 * gg0 + bb0;
        float w3 = (acc[j][3] - m1) * rs1 * gg1 + bb1;
        *(__half2*)&X[(size_t)row0 * N + col] = __float22half2_rn(make_float2(w0, w1));
        *(__half2*)&X[(size_t)row1 * N + col] = __float22half2_rn(make_float2(w2, w3));
    }
}

// ---------------- GAT attention (fp16 in, fp16 out), warp/node, online softmax ----------------
__global__ __launch_bounds__(256) void gat_attn_kernel() {
    int warp = (blockIdx.x * blockDim.x + threadIdx.x) >> 5;
    int lane = threadIdx.x & 31;
    if (warp >= TOT) return;
    int node = warp;
    int beg = g_rowptr[node], end = g_rowptr[node + 1];
    const __half2* q2 = (const __half2*)g_q16;    // 32 half2 per node
    const __half2* kv2 = (const __half2*)g_kv16;  // 64 half2 per node: k then v
    float2 qv = __half22float2(q2[(size_t)node * 32 + lane]);
    const float scale = 0.25f;  // 1/sqrt(16)
    float m = -INFINITY, denom = 0.0f, a0 = 0.0f, a1 = 0.0f;
    for (int e = beg; e < end; e++) {
        int s = g_csrc[e];
        float2 kvv = __half22float2(kv2[(size_t)s * 64 + lane]);
        float d = qv.x * kvv.x + qv.y * kvv.y;
        d += __shfl_xor_sync(0xffffffffu, d, 1);
        d += __shfl_xor_sync(0xffffffffu, d, 2);
        d += __shfl_xor_sync(0xffffffffu, d, 4);
        d *= scale;
        float mn = fmaxf(m, d);
        float f = __expf(m - mn);
        float w = __expf(d - mn);
        float2 vv = __half22float2(kv2[(size_t)s * 64 + 32 + lane]);
        denom = denom * f + w;
        a0 = a0 * f + w * vv.x;
        a1 = a1 * f + w * vv.y;
        m = mn;
    }
    float invd = 1.0f / (denom + 1e-9f);
    ((__half2*)g_buf16)[(size_t)node * 32 + lane] =
        __float22half2_rn(make_float2(a0 * invd, a1 * invd));
}

// ---------------- readout (x fp16 -> fp32) ----------------
__global__ void readout_kernel(const int* __restrict__ agent_nodes,
                               const float* __restrict__ Wr, const float* __restrict__ br)
{
    int i = blockIdx.x * blockDim.x + threadIdx.x;
    if (i >= NB * NA) return;
    int bi = i / NA, a = i % NA;
    int node = agent_nodes[bi];
    float s = br[a];
    #pragma unroll
    for (int h = 0; h < HDIM; h++)
        s += __half2float(g_x16[(size_t)node * HDIM + h]) * Wr[h * NA + a];
    g_gat[i] = s;
}

// ---------------- FC heads (fp32), 4-way ILP ----------------
__global__ __launch_bounds__(256) void fc_kernel(
    const float* __restrict__ A, const float* __restrict__ W,
    const float* __restrict__ bias, float* __restrict__ C,
    int in_dim, int out_dim, int act)
{
    __shared__ float srow[1536];
    int row = blockIdx.x;
    for (int i = threadIdx.x; i < in_dim; i += blockDim.x)
        srow[i] = A[row * in_dim + i];
    __syncthreads();
    int k4 = in_dim & ~3;
    for (int j = threadIdx.x; j < out_dim; j += blockDim.x) {
        float s0 = 0.f, s1 = 0.f, s2 = 0.f, s3 = 0.f;
        int k = 0;
        for (; k < k4; k += 4) {
            s0 += srow[k + 0] * W[(k + 0) * out_dim + j];
            s1 += srow[k + 1] * W[(k + 1) * out_dim + j];
            s2 += srow[k + 2] * W[(k + 2) * out_dim + j];
            s3 += srow[k + 3] * W[(k + 3) * out_dim + j];
        }
        for (; k < in_dim; k++) s0 += srow[k] * W[k * out_dim + j];
        float s = (bias ? bias[j] : 0.0f) + (s0 + s1) + (s2 + s3);
        if (act == 1) s = tanhf(s);
        C[row * out_dim + j] = s;
    }
}

__global__ __launch_bounds__(256) void fc_concat_kernel(
    const float* __restrict__ obs, const float* __restrict__ W,
    const float* __restrict__ bias)
{
    __shared__ float srow[1536];
    int row = blockIdx.x;
    for (int i = threadIdx.x; i < NA; i += blockDim.x) srow[i] = g_gat[row * NA + i];
    for (int i = threadIdx.x; i < OBSD; i += blockDim.x) srow[NA + i] = obs[row * OBSD + i];
    __syncthreads();
    const int in_dim = NA + OBSD;
    int k4 = in_dim & ~3;
    for (int j = threadIdx.x; j < HSD; j += blockDim.x) {
        float s0 = 0.f, s1 = 0.f, s2 = 0.f, s3 = 0.f;
        int k = 0;
        for (; k < k4; k += 4) {
            s0 += srow[k + 0] * W[(k + 0) * HSD + j];
            s1 += srow[k + 1] * W[(k + 1) * HSD + j];
            s2 += srow[k + 2] * W[(k + 2) * HSD + j];
            s3 += srow[k + 3] * W[(k + 3) * HSD + j];
        }
        for (; k < in_dim; k++) s0 += srow[k] * W[k * HSD + j];
        float s = bias[j] + (s0 + s1) + (s2 + s3);
        g_feat[row * HSD + j] = tanhf(s);
    }
}

__global__ void value_kernel(const float* __restrict__ Wvo, const float* __restrict__ bvo,
                             float* __restrict__ out)
{
    int bi = threadIdx.x;
    if (bi >= NB) return;
    float s = bvo[0];
    #pragma unroll
    for (int k = 0; k < VHD; k++) s += g_vh2[bi * VHD + k] * Wvo[k];
    out[NB * NOUTD + bi] = s;
}

// ---------------- launch ----------------
extern "C" void kernel_launch(void* const* d_in, const int* in_sizes, int n_in,
                              void* d_out, int out_size)
{
    const float* node_feats = (const float*)d_in[0];
    const float* obs        = (const float*)d_in[1];
    const int*   edge_src   = (const int*)d_in[2];
    const int*   edge_dst   = (const int*)d_in[3];
    const int*   agent_nodes= (const int*)d_in[4];
    const float* W_in = (const float*)d_in[5];
    const float* Wq   = (const float*)d_in[6];
    const float* Wk   = (const float*)d_in[7];
    const float* Wv   = (const float*)d_in[8];
    const float* Wo   = (const float*)d_in[9];
    const float* ln1g = (const float*)d_in[10];
    const float* ln1b = (const float*)d_in[11];
    const float* W1   = (const float*)d_in[12];
    const float* b1   = (const float*)d_in[13];
    const float* W2   = (const float*)d_in[14];
    const float* b2   = (const float*)d_in[15];
    const float* ln2g = (const float*)d_in[16];
    const float* ln2b = (const float*)d_in[17];
    const float* Wr   = (const float*)d_in[18];
    const float* br   = (const float*)d_in[19];
    const float* Wp1  = (const float*)d_in[20];
    const float* bp1  = (const float*)d_in[21];
    const float* Wp2  = (const float*)d_in[22];
    const float* bp2  = (const float*)d_in[23];
    const float* Wlog = (const float*)d_in[24];
    const float* blog = (const float*)d_in[25];
    const float* Wv1  = (const float*)d_in[26];
    const float* bv1  = (const float*)d_in[27];
    const float* Wv2  = (const float*)d_in[28];
    const float* bv2  = (const float*)d_in[29];
    const float* Wvo  = (const float*)d_in[30];
    const float* bvo  = (const float*)d_in[31];
    float* out = (float*)d_out;

    __half *x, *q, *kv, *buf, *hid, *nf, *w_in, *wqkv, *wo, *w1, *w2;
    float *feat, *feat2, *vh, *vh2;
    cudaGetSymbolAddress((void**)&x,    g_x16);
    cudaGetSymbolAddress((void**)&q,    g_q16);
    cudaGetSymbolAddress((void**)&kv,   g_kv16);
    cudaGetSymbolAddress((void**)&buf,  g_buf16);
    cudaGetSymbolAddress((void**)&hid,  g_hid16);
    cudaGetSymbolAddress((void**)&nf,   g_nf16);
    cudaGetSymbolAddress((void**)&w_in, g_w_in16);
    cudaGetSymbolAddress((void**)&wqkv, g_wqkv16);
    cudaGetSymbolAddress((void**)&wo,   g_wo16);
    cudaGetSymbolAddress((void**)&w1,   g_w1_16);
    cudaGetSymbolAddress((void**)&w2,   g_w2_16);
    cudaGetSymbolAddress((void**)&feat, g_feat);
    cudaGetSymbolAddress((void**)&feat2,g_feat2);
    cudaGetSymbolAddress((void**)&vh,   g_vh);
    cudaGetSymbolAddress((void**)&vh2,  g_vh2);

    const int MB = TOT / 128;  // 1000 row blocks

    // CSR build + weight conversion/packing
    zero_counts_kernel<<<(TOT + 255) / 256, 256>>>();
    count_edges_kernel<<<(NEDGE + 255) / 256, 256>>>(edge_dst);
    scan_kernel<<<1, 1024>>>();
    scatter_edges_kernel<<<(NEDGE + 255) / 256, 256>>>(edge_src, edge_dst);
    pack_qkv_f16_kernel<<<(NLAYER * HDIM * HDIM + 255) / 256, 256>>>(Wq, Wk, Wv);
    convert_f16_kernel<<<(TOT * FIN + 255) / 256, 256>>>(node_feats, nf, TOT * FIN);
    convert_f16_kernel<<<(FIN * HDIM + 255) / 256, 256>>>(W_in, w_in, FIN * HDIM);
    convert_f16_kernel<<<(NLAYER * HDIM * HDIM + 255) / 256, 256>>>(Wo, wo, NLAYER * HDIM * HDIM);
    convert_f16_kernel<<<(NLAYER * HDIM * 2 * HDIM + 255) / 256, 256>>>(W1, w1, NLAYER * HDIM * 2 * HDIM);
    convert_f16_kernel<<<(NLAYER * 2 * HDIM * HDIM + 255) / 256, 256>>>(W2, w2, NLAYER * 2 * HDIM * HDIM);

    // input projection: x = nf @ W_in   [TOT,32]@[32,64]
    gemm_f16_kernel<<<dim3(1, MB), 256>>>(nf, w_in, nullptr, x, 64, 32, 0);

    for (int l = 0; l < NLAYER; l++) {
        gemm_f16_qkv_kernel<<<dim3(3, MB), 256>>>(x, wqkv + l * HDIM * 192, q, kv);
        gat_attn_kernel<<<TOT / 8, 256>>>();
        gemm_f16_ln_kernel<<<dim3(1, MB), 256>>>(buf, wo + l * HDIM * HDIM, nullptr,
                                                 x, ln1g + l * HDIM, ln1b + l * HDIM, 64);
        gemm_f16_kernel<<<dim3(2, MB), 256>>>(x, w1 + l * HDIM * 2 * HDIM, b1 + l * 2 * HDIM,
                                              hid, 2 * HDIM, HDIM, 1);
        gemm_f16_ln_kernel<<<dim3(1, MB), 256>>>(hid, w2 + l * 2 * HDIM * HDIM, b2 + l * HDIM,
                                                 x, ln2g + l * HDIM, ln2b + l * HDIM, 128);
    }

    // heads (fp32, small)
    readout_kernel<<<(NB * NA + 255) / 256, 256>>>(agent_nodes, Wr, br);
    fc_concat_kernel<<<NB, 256>>>(obs, Wp1, bp1);
    fc_kernel<<<NB, 256>>>(feat, Wp2, bp2, feat2, HSD, HSD, 1);
    fc_kernel<<<NB, 256>>>(feat2, Wlog, blog, out, HSD, NOUTD, 0);
    fc_kernel<<<NB, 256>>>(obs, Wv1, bv1, vh, OBSD, VHD, 1);
    fc_kernel<<<NB, 256>>>(vh, Wv2, bv2, vh2, VHD, VHD, 1);
    value_kernel<<<1, 128>>>(Wvo, bvo, out);
}